// round 3
// baseline (speedup 1.0000x reference)
#include <cuda_runtime.h>
#include <cuda_bf16.h>
#include <stdint.h>

// ---------------------------------------------------------------------------
// SPMoEAdaptor fused kernel (2 soft-MoE layers + residual) for sm_103a. R2:
//  - 32 tokens/warp (2x m16 tiles) -> each B fragment feeds 2 MMAs
//  - weights packed [n][j][kk] -> 2x LDS.128 per n-tile (conflict-free, 144B row stride)
//  - gates folded into A fragments: g_e*(x@W_e) = (g_e*x)@W_e, MMA accumulates h directly
// ---------------------------------------------------------------------------

#define DD 64
#define EE 4
#define NW 264          // 256 expert cols + 4 gate cols + 4 zero pad
#define WS_U2 18        // uint2 per weight row in smem (16 payload + 2 pad = 144B)

// Prepacked weights: [layer][n][j][kk]; uint2 = {bf16x2(d=kk*16+2j,+1), bf16x2(d+8,+9)}
__device__ uint2 g_wpack[2][NW][4][4];
__device__ float g_c[2][EE][DD];   // c_e[f] = sum_d b[e,d]*W[e,d,f]

__device__ __forceinline__ uint32_t pack_bf16x2(float lo, float hi) {
    uint32_t r;
    asm("cvt.rn.bf16x2.f32 %0, %1, %2;" : "=r"(r) : "f"(hi), "f"(lo));
    return r;
}
__device__ __forceinline__ uint32_t mul_bf16x2(uint32_t a, uint32_t b) {
    uint32_t r;
    asm("mul.bf16x2 %0, %1, %2;" : "=r"(r) : "r"(a), "r"(b));
    return r;
}

// ------------------------------ prep kernel --------------------------------
__global__ void prep_kernel(const float* __restrict__ wg_a, const float* __restrict__ we_a,
                            const float* __restrict__ be_a,
                            const float* __restrict__ wg_b, const float* __restrict__ we_b,
                            const float* __restrict__ be_b) {
    const int L = blockIdx.x;
    const float* wg = L ? wg_b : wg_a;
    const float* we = L ? we_b : we_a;
    const float* be = L ? be_b : be_a;

    for (int idx = threadIdx.x; idx < NW * 16; idx += blockDim.x) {
        int n  = idx >> 4;
        int j  = (idx >> 2) & 3;
        int kk = idx & 3;
        float v[4];
#pragma unroll
        for (int h = 0; h < 4; h++) {
            int d = kk * 16 + 2 * j + (h >> 1) * 8 + (h & 1);
            float w;
            if (n < 256)        w = we[((n >> 6) * DD + d) * DD + (n & 63)]; // W_e[d][f]
            else if (n < 260)   w = wg[d * EE + (n - 256)];                  // w_gate[d][e]
            else                w = 0.0f;
            v[h] = w;
        }
        uint2 u;
        u.x = pack_bf16x2(v[0], v[1]);
        u.y = pack_bf16x2(v[2], v[3]);
        g_wpack[L][n][j][kk] = u;
    }
    for (int idx = threadIdx.x; idx < EE * DD; idx += blockDim.x) {
        int e = idx >> 6, f = idx & 63;
        float s = 0.0f;
        for (int d = 0; d < DD; d++) s += be[e * DD + d] * we[(e * DD + d) * DD + f];
        g_c[L][e][f] = s;
    }
}

// ------------------------------ MMA helpers --------------------------------
__device__ __forceinline__ void mma16816(float c[4], const uint32_t a[4], uint32_t b0, uint32_t b1) {
    asm volatile(
        "mma.sync.aligned.m16n8k16.row.col.f32.bf16.bf16.f32 "
        "{%0,%1,%2,%3}, {%4,%5,%6,%7}, {%8,%9}, {%0,%1,%2,%3};"
        : "+f"(c[0]), "+f"(c[1]), "+f"(c[2]), "+f"(c[3])
        : "r"(a[0]), "r"(a[1]), "r"(a[2]), "r"(a[3]), "r"(b0), "r"(b1));
}

__device__ __forceinline__ void softmax4(float g[4], float a, float b, float c, float d) {
    float m = fmaxf(fmaxf(a, b), fmaxf(c, d));
    float e0 = __expf(a - m), e1 = __expf(b - m), e2 = __expf(c - m), e3 = __expf(d - m);
    float inv = 1.0f / (e0 + e1 + e2 + e3);
    g[0] = e0 * inv; g[1] = e1 * inv; g[2] = e2 * inv; g[3] = e3 * inv;
}

// One full MoE layer for TWO m16 tiles (32 tokens) per warp.
__device__ __forceinline__ void moe_layer2(float h[2][8][4], const uint32_t A[2][4][4],
                                           const uint2* __restrict__ ws,
                                           const float* __restrict__ cl, int lane) {
    const int qr = lane >> 2, qc = lane & 3;
    const uint4* wl = (const uint4*)ws + qr * 9 + qc * 2;   // 9 uint4 per weight row
    const unsigned full = 0xffffffffu;
    const int qb = lane & ~3;

    // ---- gates (panel rows 256..263) ----
    float glo[2][4], ghi[2][4];
#pragma unroll
    for (int t = 0; t < 2; t++) {
        float acc[4] = {0.f, 0.f, 0.f, 0.f};
        uint4 b01 = wl[256 * 9];
        uint4 b23 = wl[256 * 9 + 1];
        mma16816(acc, A[t][0], b01.x, b01.y);
        mma16816(acc, A[t][1], b01.z, b01.w);
        mma16816(acc, A[t][2], b23.x, b23.y);
        mma16816(acc, A[t][3], b23.z, b23.w);
        float l0 = __shfl_sync(full, acc[0], qb);
        float l1 = __shfl_sync(full, acc[1], qb);
        float l2 = __shfl_sync(full, acc[0], qb + 1);
        float l3 = __shfl_sync(full, acc[1], qb + 1);
        float m0 = __shfl_sync(full, acc[2], qb);
        float m1 = __shfl_sync(full, acc[3], qb);
        float m2 = __shfl_sync(full, acc[2], qb + 1);
        float m3 = __shfl_sync(full, acc[3], qb + 1);
        softmax4(glo[t], l0, l1, l2, l3);
        softmax4(ghi[t], m0, m1, m2, m3);
    }

    // gate scalers packed bf16x2 (broadcast pair)
    uint32_t glp[2][4], ghp[2][4];
#pragma unroll
    for (int t = 0; t < 2; t++)
#pragma unroll
        for (int e = 0; e < 4; e++) {
            glp[t][e] = pack_bf16x2(glo[t][e], glo[t][e]);
            ghp[t][e] = pack_bf16x2(ghi[t][e], ghi[t][e]);
        }

#pragma unroll
    for (int t = 0; t < 2; t++)
#pragma unroll
        for (int s = 0; s < 8; s++) {
            h[t][s][0] = 0.f; h[t][s][1] = 0.f; h[t][s][2] = 0.f; h[t][s][3] = 0.f;
        }

    // ---- experts: h += (g_e * x) @ W_e, MMA-accumulated ----
#pragma unroll
    for (int e = 0; e < 4; e++) {
        uint32_t Ae[2][4][4];
#pragma unroll
        for (int t = 0; t < 2; t++)
#pragma unroll
            for (int kk = 0; kk < 4; kk++) {
                Ae[t][kk][0] = mul_bf16x2(A[t][kk][0], glp[t][e]);   // row qr
                Ae[t][kk][1] = mul_bf16x2(A[t][kk][1], ghp[t][e]);   // row qr+8
                Ae[t][kk][2] = mul_bf16x2(A[t][kk][2], glp[t][e]);
                Ae[t][kk][3] = mul_bf16x2(A[t][kk][3], ghp[t][e]);
            }
#pragma unroll
        for (int s = 0; s < 8; s++) {
            const uint4* p = wl + (e * 8 + s) * 8 * 9;
            uint4 b01 = p[0];
            uint4 b23 = p[1];
#pragma unroll
            for (int t = 0; t < 2; t++) {
                mma16816(h[t][s], Ae[t][0], b01.x, b01.y);
                mma16816(h[t][s], Ae[t][1], b01.z, b01.w);
                mma16816(h[t][s], Ae[t][2], b23.x, b23.y);
                mma16816(h[t][s], Ae[t][3], b23.z, b23.w);
            }
        }
    }

    // ---- bias correction: h -= sum_e g_e * c_e ----
#pragma unroll
    for (int s = 0; s < 8; s++) {
        int f = s * 8 + qc * 2;
#pragma unroll
        for (int e = 0; e < 4; e++) {
            float2 ce = *(const float2*)(cl + e * 64 + f);
#pragma unroll
            for (int t = 0; t < 2; t++) {
                h[t][s][0] = fmaf(-glo[t][e], ce.x, h[t][s][0]);
                h[t][s][1] = fmaf(-glo[t][e], ce.y, h[t][s][1]);
                h[t][s][2] = fmaf(-ghi[t][e], ce.x, h[t][s][2]);
                h[t][s][3] = fmaf(-ghi[t][e], ce.y, h[t][s][3]);
            }
        }
    }
}

// ------------------------------ main kernel --------------------------------
__global__ __launch_bounds__(256, 1)
void moe_main_kernel(const float* __restrict__ x, float* __restrict__ out, int Ntok) {
    extern __shared__ __align__(16) uint2 smem[];
    uint2* ws0 = smem;
    uint2* ws1 = smem + NW * WS_U2;
    float* cs  = (float*)(smem + 2 * NW * WS_U2);   // [2][256]

    for (int idx = threadIdx.x; idx < NW * 16; idx += 256) {
        int n = idx >> 4, r = idx & 15;
        ws0[n * WS_U2 + r] = ((const uint2*)g_wpack[0])[idx];
        ws1[n * WS_U2 + r] = ((const uint2*)g_wpack[1])[idx];
    }
    for (int idx = threadIdx.x; idx < 512; idx += 256)
        cs[idx] = ((const float*)g_c)[idx];
    __syncthreads();

    const int warp = threadIdx.x >> 5;
    const int lane = threadIdx.x & 31;
    const int qr = lane >> 2;
    const int qc = lane & 3;
    const int tokbase = blockIdx.x * 256 + warp * 32;

    // ---- layer 1 A fragments straight from gmem (fp32 -> bf16), 2 tiles ----
    uint32_t A1[2][4][4];
#pragma unroll
    for (int t = 0; t < 2; t++) {
        int ra = min(tokbase + t * 16 + qr, Ntok - 1);
        int rb = min(tokbase + t * 16 + qr + 8, Ntok - 1);
        const float* xa = x + (size_t)ra * DD;
        const float* xb = x + (size_t)rb * DD;
#pragma unroll
        for (int kk = 0; kk < 4; kk++) {
            int c = kk * 16 + qc * 2;
            float2 v0 = *(const float2*)(xa + c);
            float2 v1 = *(const float2*)(xb + c);
            float2 v2 = *(const float2*)(xa + c + 8);
            float2 v3 = *(const float2*)(xb + c + 8);
            A1[t][kk][0] = pack_bf16x2(v0.x, v0.y);
            A1[t][kk][1] = pack_bf16x2(v1.x, v1.y);
            A1[t][kk][2] = pack_bf16x2(v2.x, v2.y);
            A1[t][kk][3] = pack_bf16x2(v3.x, v3.y);
        }
    }

    // ---- layer 1 ----
    float h1[2][8][4];
    moe_layer2(h1, A1, ws0, cs, lane);

    // ---- h fragments ARE layer-2 A fragments ----
    uint32_t A2[2][4][4];
#pragma unroll
    for (int t = 0; t < 2; t++)
#pragma unroll
        for (int kk = 0; kk < 4; kk++) {
            A2[t][kk][0] = pack_bf16x2(h1[t][2 * kk][0],     h1[t][2 * kk][1]);
            A2[t][kk][1] = pack_bf16x2(h1[t][2 * kk][2],     h1[t][2 * kk][3]);
            A2[t][kk][2] = pack_bf16x2(h1[t][2 * kk + 1][0], h1[t][2 * kk + 1][1]);
            A2[t][kk][3] = pack_bf16x2(h1[t][2 * kk + 1][2], h1[t][2 * kk + 1][3]);
        }

    // ---- layer 2 ----
    float h2[2][8][4];
    moe_layer2(h2, A2, ws1, cs + 256, lane);

    // ---- residual (exact fp32) + store ----
#pragma unroll
    for (int t = 0; t < 2; t++) {
        int rowa = tokbase + t * 16 + qr;
        int rowb = rowa + 8;
        bool va = rowa < Ntok;
        bool vb = rowb < Ntok;
#pragma unroll
        for (int s = 0; s < 8; s++) {
            int f = s * 8 + qc * 2;
            if (va) {
                float2 xr = *(const float2*)(x + (size_t)rowa * DD + f);
                float2 o;
                o.x = h2[t][s][0] + xr.x;
                o.y = h2[t][s][1] + xr.y;
                *(float2*)(out + (size_t)rowa * DD + f) = o;
            }
            if (vb) {
                float2 xr = *(const float2*)(x + (size_t)rowb * DD + f);
                float2 o;
                o.x = h2[t][s][2] + xr.x;
                o.y = h2[t][s][3] + xr.y;
                *(float2*)(out + (size_t)rowb * DD + f) = o;
            }
        }
    }
}

// ------------------------------ launch -------------------------------------
extern "C" void kernel_launch(void* const* d_in, const int* in_sizes, int n_in,
                              void* d_out, int out_size) {
    const float* x    = (const float*)d_in[0];
    const float* wg_a = (const float*)d_in[1];
    const float* we_a = (const float*)d_in[2];
    const float* be_a = (const float*)d_in[3];
    const float* wg_b = (const float*)d_in[4];
    const float* we_b = (const float*)d_in[5];
    const float* be_b = (const float*)d_in[6];
    const int Ntok = in_sizes[0] / DD;

    prep_kernel<<<2, 256>>>(wg_a, we_a, be_a, wg_b, we_b, be_b);

    const int smem_bytes = 2 * NW * WS_U2 * (int)sizeof(uint2) + 512 * (int)sizeof(float);
    cudaFuncSetAttribute(moe_main_kernel, cudaFuncAttributeMaxDynamicSharedMemorySize, smem_bytes);

    const int grid = (Ntok + 255) / 256;
    moe_main_kernel<<<grid, 256, smem_bytes>>>(x, (float*)d_out, Ntok);
}

// round 8
// speedup vs baseline: 1.0408x; 1.0408x over previous
#include <cuda_runtime.h>
#include <cuda_bf16.h>
#include <stdint.h>

// ---------------------------------------------------------------------------
// SPMoEAdaptor fused kernel (2 soft-MoE layers + residual) for sm_103a. R7:
// R1 structure (16 tokens/warp, ~128 regs, 2 CTA/SM) + R2's conflict-free
// [n][j][kk] weight packing read as 2x LDS.128 per n-tile (144B row stride).
// Fixes R1's systematic 2-way bank conflict on every B-fragment load.
// ---------------------------------------------------------------------------

#define DD 64
#define EE 4
#define NW 264          // 256 expert cols + 4 gate cols + 4 zero pad
#define WS_U2 18        // uint2 per weight row in smem (16 payload + 2 pad = 144B)
#define WS_U4 9         // uint4 per weight row

// Prepacked weights: [layer][n][j][kk]; uint2 = {bf16x2(d=kk*16+2j,+1), bf16x2(d+8,+9)}
__device__ uint2 g_wpack[2][NW][4][4];
__device__ float g_c[2][EE][DD];   // c_e[f] = sum_d b[e,d]*W[e,d,f]

__device__ __forceinline__ uint32_t pack_bf16x2(float lo, float hi) {
    uint32_t r;
    asm("cvt.rn.bf16x2.f32 %0, %1, %2;" : "=r"(r) : "f"(hi), "f"(lo));
    return r;
}

// ------------------------------ prep kernel --------------------------------
__global__ void prep_kernel(const float* __restrict__ wg_a, const float* __restrict__ we_a,
                            const float* __restrict__ be_a,
                            const float* __restrict__ wg_b, const float* __restrict__ we_b,
                            const float* __restrict__ be_b) {
    const int L = blockIdx.x;
    const float* wg = L ? wg_b : wg_a;
    const float* we = L ? we_b : we_a;
    const float* be = L ? be_b : be_a;

    for (int idx = threadIdx.x; idx < NW * 16; idx += blockDim.x) {
        int n  = idx >> 4;
        int j  = (idx >> 2) & 3;
        int kk = idx & 3;
        float v[4];
#pragma unroll
        for (int h = 0; h < 4; h++) {
            int d = kk * 16 + 2 * j + (h >> 1) * 8 + (h & 1);
            float w;
            if (n < 256)        w = we[((n >> 6) * DD + d) * DD + (n & 63)]; // W_e[d][f]
            else if (n < 260)   w = wg[d * EE + (n - 256)];                  // w_gate[d][e]
            else                w = 0.0f;
            v[h] = w;
        }
        uint2 u;
        u.x = pack_bf16x2(v[0], v[1]);
        u.y = pack_bf16x2(v[2], v[3]);
        g_wpack[L][n][j][kk] = u;
    }
    for (int idx = threadIdx.x; idx < EE * DD; idx += blockDim.x) {
        int e = idx >> 6, f = idx & 63;
        float s = 0.0f;
        for (int d = 0; d < DD; d++) s += be[e * DD + d] * we[(e * DD + d) * DD + f];
        g_c[L][e][f] = s;
    }
}

// ------------------------------ MMA helpers --------------------------------
__device__ __forceinline__ void mma16816(float c[4], const uint32_t a[4], uint32_t b0, uint32_t b1) {
    asm volatile(
        "mma.sync.aligned.m16n8k16.row.col.f32.bf16.bf16.f32 "
        "{%0,%1,%2,%3}, {%4,%5,%6,%7}, {%8,%9}, {%0,%1,%2,%3};"
        : "+f"(c[0]), "+f"(c[1]), "+f"(c[2]), "+f"(c[3])
        : "r"(a[0]), "r"(a[1]), "r"(a[2]), "r"(a[3]), "r"(b0), "r"(b1));
}

// One [16 x 8] n-tile over full K=64: 2 conflict-free LDS.128 + 4 MMAs.
// wl is pre-offset: (const uint4*)ws + qr*WS_U4 + qc*2 ; nbase in weight rows.
__device__ __forceinline__ void ntile(float acc[4], const uint32_t A[4][4],
                                      const uint4* __restrict__ wl, int nbase) {
    acc[0] = acc[1] = acc[2] = acc[3] = 0.0f;
    const uint4* p = wl + nbase * WS_U4;
    uint4 b01 = p[0];
    uint4 b23 = p[1];
    mma16816(acc, A[0], b01.x, b01.y);
    mma16816(acc, A[1], b01.z, b01.w);
    mma16816(acc, A[2], b23.x, b23.y);
    mma16816(acc, A[3], b23.z, b23.w);
}

__device__ __forceinline__ void softmax4(float g[4], float a, float b, float c, float d) {
    float m = fmaxf(fmaxf(a, b), fmaxf(c, d));
    float e0 = __expf(a - m), e1 = __expf(b - m), e2 = __expf(c - m), e3 = __expf(d - m);
    float inv = 1.0f / (e0 + e1 + e2 + e3);
    g[0] = e0 * inv; g[1] = e1 * inv; g[2] = e2 * inv; g[3] = e3 * inv;
}

// One full MoE layer for one m16 tile (16 tokens) per warp.
__device__ __forceinline__ void moe_layer(float h[8][4], const uint32_t A[4][4],
                                          const uint4* __restrict__ wl,
                                          const float* __restrict__ cl, int lane) {
    const unsigned full = 0xffffffffu;
    const int qb = lane & ~3;
    const int qc = lane & 3;

    // ---- gates (panel rows 256..263) ----
    float glo[4], ghi[4];
    {
        float acc[4];
        ntile(acc, A, wl, 256);
        float l0 = __shfl_sync(full, acc[0], qb);
        float l1 = __shfl_sync(full, acc[1], qb);
        float l2 = __shfl_sync(full, acc[0], qb + 1);
        float l3 = __shfl_sync(full, acc[1], qb + 1);
        float m0 = __shfl_sync(full, acc[2], qb);
        float m1 = __shfl_sync(full, acc[3], qb);
        float m2 = __shfl_sync(full, acc[2], qb + 1);
        float m3 = __shfl_sync(full, acc[3], qb + 1);
        softmax4(glo, l0, l1, l2, l3);
        softmax4(ghi, m0, m1, m2, m3);
    }

#pragma unroll
    for (int s = 0; s < 8; s++) {
        h[s][0] = 0.f; h[s][1] = 0.f; h[s][2] = 0.f; h[s][3] = 0.f;
    }

    // ---- experts: h += g_e * (x @ W_e) ----
#pragma unroll
    for (int e = 0; e < 4; e++) {
#pragma unroll
        for (int s = 0; s < 8; s++) {
            float acc[4];
            ntile(acc, A, wl, (e * 8 + s) * 8);
            h[s][0] = fmaf(glo[e], acc[0], h[s][0]);
            h[s][1] = fmaf(glo[e], acc[1], h[s][1]);
            h[s][2] = fmaf(ghi[e], acc[2], h[s][2]);
            h[s][3] = fmaf(ghi[e], acc[3], h[s][3]);
        }
    }

    // ---- bias correction: h -= sum_e g_e * c_e ----
#pragma unroll
    for (int s = 0; s < 8; s++) {
        int f = s * 8 + qc * 2;
#pragma unroll
        for (int e = 0; e < 4; e++) {
            float2 ce = *(const float2*)(cl + e * 64 + f);
            h[s][0] = fmaf(-glo[e], ce.x, h[s][0]);
            h[s][1] = fmaf(-glo[e], ce.y, h[s][1]);
            h[s][2] = fmaf(-ghi[e], ce.x, h[s][2]);
            h[s][3] = fmaf(-ghi[e], ce.y, h[s][3]);
        }
    }
}

// ------------------------------ main kernel --------------------------------
__global__ __launch_bounds__(256, 2)
void moe_main_kernel(const float* __restrict__ x, float* __restrict__ out, int Ntok) {
    extern __shared__ __align__(16) uint2 smem[];
    uint2* ws0 = smem;
    uint2* ws1 = smem + NW * WS_U2;
    float* cs  = (float*)(smem + 2 * NW * WS_U2);   // [2][256]

    for (int idx = threadIdx.x; idx < NW * 16; idx += 256) {
        int n = idx >> 4, r = idx & 15;
        ws0[n * WS_U2 + r] = ((const uint2*)g_wpack[0])[idx];
        ws1[n * WS_U2 + r] = ((const uint2*)g_wpack[1])[idx];
    }
    for (int idx = threadIdx.x; idx < 512; idx += 256)
        cs[idx] = ((const float*)g_c)[idx];
    __syncthreads();

    const int warp = threadIdx.x >> 5;
    const int lane = threadIdx.x & 31;
    const int qr = lane >> 2;
    const int qc = lane & 3;
    const int tok0 = blockIdx.x * 128 + warp * 16 + qr;   // rows tok0 and tok0+8

    const uint4* wl0 = (const uint4*)ws0 + qr * WS_U4 + qc * 2;
    const uint4* wl1 = (const uint4*)ws1 + qr * WS_U4 + qc * 2;

    const int ta = min(tok0, Ntok - 1);
    const int tb = min(tok0 + 8, Ntok - 1);
    const float* xa = x + (size_t)ta * DD;
    const float* xb = x + (size_t)tb * DD;

    // ---- layer 1 A fragments straight from gmem (fp32 -> bf16) ----
    uint32_t A1[4][4];
#pragma unroll
    for (int kk = 0; kk < 4; kk++) {
        int c = kk * 16 + qc * 2;
        float2 v0 = *(const float2*)(xa + c);
        float2 v1 = *(const float2*)(xb + c);
        float2 v2 = *(const float2*)(xa + c + 8);
        float2 v3 = *(const float2*)(xb + c + 8);
        A1[kk][0] = pack_bf16x2(v0.x, v0.y);
        A1[kk][1] = pack_bf16x2(v1.x, v1.y);
        A1[kk][2] = pack_bf16x2(v2.x, v2.y);
        A1[kk][3] = pack_bf16x2(v3.x, v3.y);
    }

    // ---- layer 1 ----
    float h1[8][4];
    moe_layer(h1, A1, wl0, cs, lane);

    // ---- h fragments ARE layer-2 A fragments (same lane map) ----
    uint32_t A2[4][4];
#pragma unroll
    for (int kk = 0; kk < 4; kk++) {
        A2[kk][0] = pack_bf16x2(h1[2 * kk][0],     h1[2 * kk][1]);
        A2[kk][1] = pack_bf16x2(h1[2 * kk][2],     h1[2 * kk][3]);
        A2[kk][2] = pack_bf16x2(h1[2 * kk + 1][0], h1[2 * kk + 1][1]);
        A2[kk][3] = pack_bf16x2(h1[2 * kk + 1][2], h1[2 * kk + 1][3]);
    }

    // ---- layer 2 ----
    float h2[8][4];
    moe_layer(h2, A2, wl1, cs + 256, lane);

    // ---- residual (exact fp32 reload, L2-hot) + store ----
    const bool va = (tok0 < Ntok);
    const bool vb = (tok0 + 8 < Ntok);
#pragma unroll
    for (int s = 0; s < 8; s++) {
        int f = s * 8 + qc * 2;
        if (va) {
            float2 xr = *(const float2*)(x + (size_t)tok0 * DD + f);
            float2 o;
            o.x = h2[s][0] + xr.x;
            o.y = h2[s][1] + xr.y;
            *(float2*)(out + (size_t)tok0 * DD + f) = o;
        }
        if (vb) {
            float2 xr = *(const float2*)(x + (size_t)(tok0 + 8) * DD + f);
            float2 o;
            o.x = h2[s][2] + xr.x;
            o.y = h2[s][3] + xr.y;
            *(float2*)(out + (size_t)(tok0 + 8) * DD + f) = o;
        }
    }
}

// ------------------------------ launch -------------------------------------
extern "C" void kernel_launch(void* const* d_in, const int* in_sizes, int n_in,
                              void* d_out, int out_size) {
    const float* x    = (const float*)d_in[0];
    const float* wg_a = (const float*)d_in[1];
    const float* we_a = (const float*)d_in[2];
    const float* be_a = (const float*)d_in[3];
    const float* wg_b = (const float*)d_in[4];
    const float* we_b = (const float*)d_in[5];
    const float* be_b = (const float*)d_in[6];
    const int Ntok = in_sizes[0] / DD;

    prep_kernel<<<2, 256>>>(wg_a, we_a, be_a, wg_b, we_b, be_b);

    const int smem_bytes = 2 * NW * WS_U2 * (int)sizeof(uint2) + 512 * (int)sizeof(float);
    cudaFuncSetAttribute(moe_main_kernel, cudaFuncAttributeMaxDynamicSharedMemorySize, smem_bytes);

    const int grid = (Ntok + 127) / 128;
    moe_main_kernel<<<grid, 256, smem_bytes>>>(x, (float*)d_out, Ntok);
}

// round 11
// speedup vs baseline: 1.4297x; 1.3737x over previous
#include <cuda_runtime.h>
#include <cuda_bf16.h>
#include <stdint.h>

// ---------------------------------------------------------------------------
// SPMoEAdaptor fused (2 soft-MoE layers + residual), sm_103a. R9: n-split
// dataflow — each warp owns an 8-col f-slice of B (all 4 experts) in
// REGISTERS; tokens stream through smem; A-fragments via ldmatrix; coalesced
// global I/O. Eliminates the per-warp B-through-LDS wall of R1/R7.
// ---------------------------------------------------------------------------

#define DD 64
#define NW 264           // 256 expert cols + 4 gate cols + 4 zero pad
#define RS 72            // bf16 row stride in token buffers (144B, LDSM conflict-free)

// Prepacked weights: [layer][n][j][kk]; uint2 = {bf16x2(d=kk*16+2j,+1), bf16x2(d+8,+9)}
__device__ __align__(16) uint2 g_wpack[2][NW][4][4];
__device__ float g_c[2][4][DD];   // c_e[f] = sum_d b[e,d]*W[e,d,f]

__device__ __forceinline__ uint32_t pack_bf16x2(float lo, float hi) {
    uint32_t r; asm("cvt.rn.bf16x2.f32 %0, %1, %2;" : "=r"(r) : "f"(hi), "f"(lo)); return r;
}
__device__ __forceinline__ float bf_lo(uint32_t u) { return __uint_as_float(u << 16); }
__device__ __forceinline__ float bf_hi(uint32_t u) { return __uint_as_float(u & 0xffff0000u); }

__device__ __forceinline__ uint32_t smem_u32(const void* p) {
    uint32_t a; asm("{ .reg .u64 t; cvta.to.shared.u64 t, %1; cvt.u32.u64 %0, t; }" : "=r"(a) : "l"(p)); return a;
}
__device__ __forceinline__ void sts32(uint32_t a, uint32_t v) {
    asm volatile("st.shared.b32 [%0], %1;" :: "r"(a), "r"(v) : "memory");
}
__device__ __forceinline__ void sts64(uint32_t a, uint32_t v0, uint32_t v1) {
    asm volatile("st.shared.v2.b32 [%0], {%1,%2};" :: "r"(a), "r"(v0), "r"(v1) : "memory");
}
__device__ __forceinline__ uint2 lds64(uint32_t a) {
    uint2 v; asm volatile("ld.shared.v2.b32 {%0,%1}, [%2];" : "=r"(v.x), "=r"(v.y) : "r"(a)); return v;
}
__device__ __forceinline__ float4 ldsf4(uint32_t a) {
    float4 v; asm volatile("ld.shared.v4.f32 {%0,%1,%2,%3}, [%4];"
        : "=f"(v.x), "=f"(v.y), "=f"(v.z), "=f"(v.w) : "r"(a)); return v;
}
__device__ __forceinline__ void stsf4(uint32_t a, float4 v) {
    asm volatile("st.shared.v4.f32 [%0], {%1,%2,%3,%4};" :: "r"(a), "f"(v.x), "f"(v.y), "f"(v.z), "f"(v.w) : "memory");
}
__device__ __forceinline__ float2 ldsf2(uint32_t a) {
    float2 v; asm volatile("ld.shared.v2.f32 {%0,%1}, [%2];" : "=f"(v.x), "=f"(v.y) : "r"(a)); return v;
}
__device__ __forceinline__ void ldsm_x4(uint32_t r[4], uint32_t a) {
    asm volatile("ldmatrix.sync.aligned.m8n8.x4.shared.b16 {%0,%1,%2,%3}, [%4];"
        : "=r"(r[0]), "=r"(r[1]), "=r"(r[2]), "=r"(r[3]) : "r"(a));
}
__device__ __forceinline__ void mma16816(float c[4], const uint32_t a[4], uint32_t b0, uint32_t b1) {
    asm volatile(
        "mma.sync.aligned.m16n8k16.row.col.f32.bf16.bf16.f32 "
        "{%0,%1,%2,%3}, {%4,%5,%6,%7}, {%8,%9}, {%0,%1,%2,%3};"
        : "+f"(c[0]), "+f"(c[1]), "+f"(c[2]), "+f"(c[3])
        : "r"(a[0]), "r"(a[1]), "r"(a[2]), "r"(a[3]), "r"(b0), "r"(b1));
}

// ------------------------------ prep kernel --------------------------------
__global__ void prep_kernel(const float* __restrict__ wg_a, const float* __restrict__ we_a,
                            const float* __restrict__ be_a,
                            const float* __restrict__ wg_b, const float* __restrict__ we_b,
                            const float* __restrict__ be_b) {
    const int L = blockIdx.x;
    const float* wg = L ? wg_b : wg_a;
    const float* we = L ? we_b : we_a;
    const float* be = L ? be_b : be_a;

    for (int idx = threadIdx.x; idx < NW * 16; idx += blockDim.x) {
        int n  = idx >> 4;
        int j  = (idx >> 2) & 3;
        int kk = idx & 3;
        float v[4];
#pragma unroll
        for (int h = 0; h < 4; h++) {
            int d = kk * 16 + 2 * j + (h >> 1) * 8 + (h & 1);
            float w;
            if (n < 256)        w = we[((n >> 6) * DD + d) * DD + (n & 63)]; // W_e[d][f]
            else if (n < 260)   w = wg[d * 4 + (n - 256)];                   // w_gate[d][e]
            else                w = 0.0f;
            v[h] = w;
        }
        uint2 u;
        u.x = pack_bf16x2(v[0], v[1]);
        u.y = pack_bf16x2(v[2], v[3]);
        g_wpack[L][n][j][kk] = u;
    }
    for (int idx = threadIdx.x; idx < 4 * DD; idx += blockDim.x) {
        int e = idx >> 6, f = idx & 63;
        float s = 0.0f;
        for (int d = 0; d < DD; d++) s += be[e * DD + d] * we[(e * DD + d) * DD + f];
        g_c[L][e][f] = s;
    }
}

// ------------------------------ main kernel --------------------------------
__global__ __launch_bounds__(256, 2)
void moe_main_kernel(const float* __restrict__ x, float* __restrict__ out, int Ntok) {
    extern __shared__ __align__(16) uint8_t smraw[];
    const uint32_t base = smem_u32(smraw);
    const uint32_t BUFA = base;                  // [128][RS] bf16 (x / h2)
    const uint32_t BUFB = base + 128 * RS * 2;   // [128][RS] bf16 (h1)
    const uint32_t GSM  = BUFB + 128 * RS * 2;   // [128][4] f32 gates
    const uint32_t CSM  = GSM + 128 * 16;        // [2][4][64] f32 bias

    const int tid  = threadIdx.x;
    const int w    = tid >> 5;
    const int lane = tid & 31;
    const int qr   = lane >> 2;
    const int qc   = lane & 3;
    const long tok0 = (long)blockIdx.x * 128;

    for (int i = tid; i < 512; i += 256)
        sts32(CSM + i * 4, ((const uint32_t*)g_c)[i]);

    // ---- stage x -> BUFA (bf16), fully coalesced ----
#pragma unroll
    for (int i = 0; i < 8; i++) {
        int idx = w * 1024 + i * 128 + lane * 4;     // 0..8191 floats
        int row = idx >> 6, col = idx & 63;
        long r = tok0 + row;
        float4 v = (r < Ntok) ? *(const float4*)(x + r * 64 + col)
                              : make_float4(0.f, 0.f, 0.f, 0.f);
        sts64(BUFA + (row * RS + col) * 2, pack_bf16x2(v.x, v.y), pack_bf16x2(v.z, v.w));
    }
    __syncthreads();

    const uint32_t lrow = (uint32_t)(lane & 15) * (RS * 2) + (uint32_t)(lane >> 4) * 16;
    const uint4* gw4 = (const uint4*)g_wpack;    // 8 uint4 per n-row

#pragma unroll
    for (int L = 0; L < 2; L++) {
        const uint32_t inb  = (L == 0) ? BUFA : BUFB;
        const uint32_t outb = (L == 0) ? BUFB : BUFA;
        const uint32_t wbase = (uint32_t)L * NW * 8;

        // ---- expert B-slice into registers: n = e*64 + 8w + qr ----
        uint4 Bx[4][2];
#pragma unroll
        for (int e = 0; e < 4; e++) {
            const uint4* p = gw4 + wbase + (uint32_t)(e * 64 + 8 * w + qr) * 8 + qc * 2;
            Bx[e][0] = p[0];
            Bx[e][1] = p[1];
        }

        // ---- gate phase: warp w handles m-tile w ----
        {
            const uint4* pg = gw4 + wbase + (uint32_t)(256 + qr) * 8 + qc * 2;
            uint4 Bg0 = pg[0], Bg1 = pg[1];
            uint32_t Af[4][4];
            uint32_t ab = inb + (uint32_t)(w * 16) * (RS * 2) + lrow;
#pragma unroll
            for (int c = 0; c < 4; c++) ldsm_x4(Af[c], ab + c * 32);
            float acc[4] = {0.f, 0.f, 0.f, 0.f};
            mma16816(acc, Af[0], Bg0.x, Bg0.y);
            mma16816(acc, Af[1], Bg0.z, Bg0.w);
            mma16816(acc, Af[2], Bg1.x, Bg1.y);
            mma16816(acc, Af[3], Bg1.z, Bg1.w);
            const unsigned full = 0xffffffffu;
            const int qb = lane & ~3;
            float l0 = __shfl_sync(full, acc[0], qb);
            float l1 = __shfl_sync(full, acc[1], qb);
            float l2 = __shfl_sync(full, acc[0], qb + 1);
            float l3 = __shfl_sync(full, acc[1], qb + 1);
            float m0 = __shfl_sync(full, acc[2], qb);
            float m1 = __shfl_sync(full, acc[3], qb);
            float m2 = __shfl_sync(full, acc[2], qb + 1);
            float m3 = __shfl_sync(full, acc[3], qb + 1);
            float mxl = fmaxf(fmaxf(l0, l1), fmaxf(l2, l3));
            float e0 = __expf(l0 - mxl), e1 = __expf(l1 - mxl), e2 = __expf(l2 - mxl), e3 = __expf(l3 - mxl);
            float inv = 1.0f / (e0 + e1 + e2 + e3);
            float4 glo = make_float4(e0 * inv, e1 * inv, e2 * inv, e3 * inv);
            float mxh = fmaxf(fmaxf(m0, m1), fmaxf(m2, m3));
            float f0 = __expf(m0 - mxh), f1 = __expf(m1 - mxh), f2 = __expf(m2 - mxh), f3 = __expf(m3 - mxh);
            float inh = 1.0f / (f0 + f1 + f2 + f3);
            float4 ghi = make_float4(f0 * inh, f1 * inh, f2 * inh, f3 * inh);
            if (qc == 0) {
                stsf4(GSM + (uint32_t)(w * 16 + qr) * 16, glo);
                stsf4(GSM + (uint32_t)(w * 16 + qr + 8) * 16, ghi);
            }
        }
        __syncthreads();

        // ---- bias slice for this warp's f-cols ----
        float2 cf[4];
#pragma unroll
        for (int e = 0; e < 4; e++)
            cf[e] = ldsf2(CSM + ((uint32_t)L * 256 + e * 64 + 8 * w + 2 * qc) * 4);

        // ---- main: all 8 m-tiles through this warp's f-slice ----
#pragma unroll
        for (int mt = 0; mt < 8; mt++) {
            uint32_t Af[4][4];
            uint32_t ab = inb + (uint32_t)(mt * 16) * (RS * 2) + lrow;
#pragma unroll
            for (int c = 0; c < 4; c++) ldsm_x4(Af[c], ab + c * 32);
            float4 gl = ldsf4(GSM + (uint32_t)(mt * 16 + qr) * 16);
            float4 gh = ldsf4(GSM + (uint32_t)(mt * 16 + qr + 8) * 16);
            const float gle[4] = {gl.x, gl.y, gl.z, gl.w};
            const float ghe[4] = {gh.x, gh.y, gh.z, gh.w};
            float h0 = 0.f, h1 = 0.f, h2 = 0.f, h3 = 0.f;
#pragma unroll
            for (int e = 0; e < 4; e++) {
                float Y[4] = {0.f, 0.f, 0.f, 0.f};
                mma16816(Y, Af[0], Bx[e][0].x, Bx[e][0].y);
                mma16816(Y, Af[1], Bx[e][0].z, Bx[e][0].w);
                mma16816(Y, Af[2], Bx[e][1].x, Bx[e][1].y);
                mma16816(Y, Af[3], Bx[e][1].z, Bx[e][1].w);
                h0 = fmaf(gle[e], Y[0], h0);
                h1 = fmaf(gle[e], Y[1], h1);
                h2 = fmaf(ghe[e], Y[2], h2);
                h3 = fmaf(ghe[e], Y[3], h3);
            }
#pragma unroll
            for (int e = 0; e < 4; e++) {
                h0 = fmaf(-gle[e], cf[e].x, h0);
                h1 = fmaf(-gle[e], cf[e].y, h1);
                h2 = fmaf(-ghe[e], cf[e].x, h2);
                h3 = fmaf(-ghe[e], cf[e].y, h3);
            }
            uint32_t oc = (uint32_t)(8 * w + 2 * qc) * 2;
            sts32(outb + (uint32_t)(mt * 16 + qr) * (RS * 2) + oc, pack_bf16x2(h0, h1));
            sts32(outb + (uint32_t)(mt * 16 + qr + 8) * (RS * 2) + oc, pack_bf16x2(h2, h3));
        }
        __syncthreads();
    }

    // ---- epilogue: h2 (BUFA) + residual x (fp32, L2-hot) -> out, coalesced ----
#pragma unroll
    for (int i = 0; i < 8; i++) {
        int idx = w * 1024 + i * 128 + lane * 4;
        int row = idx >> 6, col = idx & 63;
        long r = tok0 + row;
        if (r < Ntok) {
            uint2 hp = lds64(BUFA + (row * RS + col) * 2);
            float4 xr = *(const float4*)(x + r * 64 + col);
            float4 o = make_float4(bf_lo(hp.x) + xr.x, bf_hi(hp.x) + xr.y,
                                   bf_lo(hp.y) + xr.z, bf_hi(hp.y) + xr.w);
            *(float4*)(out + r * 64 + col) = o;
        }
    }
}

// ------------------------------ launch -------------------------------------
extern "C" void kernel_launch(void* const* d_in, const int* in_sizes, int n_in,
                              void* d_out, int out_size) {
    const float* x    = (const float*)d_in[0];
    const float* wg_a = (const float*)d_in[1];
    const float* we_a = (const float*)d_in[2];
    const float* be_a = (const float*)d_in[3];
    const float* wg_b = (const float*)d_in[4];
    const float* we_b = (const float*)d_in[5];
    const float* be_b = (const float*)d_in[6];
    const int Ntok = in_sizes[0] / DD;

    prep_kernel<<<2, 256>>>(wg_a, we_a, be_a, wg_b, we_b, be_b);

    const int smem_bytes = 2 * 128 * RS * 2 + 128 * 16 + 512 * 4;  // 41472
    cudaFuncSetAttribute(moe_main_kernel, cudaFuncAttributeMaxDynamicSharedMemorySize, smem_bytes);

    const int grid = (Ntok + 127) / 128;
    moe_main_kernel<<<grid, 256, smem_bytes>>>(x, (float*)d_out, Ntok);
}